// round 15
// baseline (speedup 1.0000x reference)
#include <cuda_runtime.h>
#include <cuda_fp16.h>
#include <cstdint>
#include <math.h>

#define SS 2048
#define DD 1024
#define HH 8

// ---------------- scratch (__device__ globals; allocation-free rule) -------
__device__ __half g_hid_hi[SS * DD];
__device__ __half g_hid_lo[SS * DD];
__device__ __half g_w2t_hi[DD * DD];
__device__ __half g_w2t_lo[DD * DD];
__device__ __half g_awt_hi[HH * DD * DD];
__device__ __half g_awt_lo[HH * DD * DD];
__device__ __half g_x_hi[SS * DD];
__device__ __half g_x_lo[SS * DD];
__device__ __half g_xt[DD * SS];
__device__ __half g_owt[DD * HH * DD];
__device__ __half g_rel_hi[SS * DD];
__device__ __half g_rel_lo[SS * DD];
__device__ __half g_Q_hi[HH * SS * DD];
__device__ __half g_Q_lo[HH * SS * DD];
__device__ float  g_logits[(size_t)HH * SS * SS];
__device__ __half g_probs[(size_t)HH * SS * SS];
__device__ __half g_ctx[(size_t)SS * HH * DD];

// ---------------- helpers ---------------------------------------------------
__device__ __forceinline__ uint32_t smem_u32(const void* p) {
    uint32_t a;
    asm("{ .reg .u64 t; cvta.to.shared.u64 t, %1; cvt.u32.u64 %0, t; }"
        : "=r"(a) : "l"(p));
    return a;
}
// k-permutation (within 32-groups) for fp16 m16n8k16 fragments.
// inverse: natural k stored at position p
__device__ __forceinline__ int invp(int p) {            // p in [0,32)
    return (p & 1) | (((p >> 3) & 3) << 1) | (((p >> 1) & 1) << 3) |
           (((p >> 2) & 1) << 4);
}
__device__ __forceinline__ uint32_t pack2(float x, float y) {
    __half hx = __float2half_rn(x), hy = __float2half_rn(y);
    return (uint32_t)__half_as_ushort(hx) |
           ((uint32_t)__half_as_ushort(hy) << 16);
}
__device__ __forceinline__ float lo_of(float v) {
    return v - __half2float(__float2half_rn(v));
}
__device__ __forceinline__ void mma16(float* d, uint32_t a0, uint32_t a1,
                                      uint32_t a2, uint32_t a3, uint32_t b0,
                                      uint32_t b1) {
    asm volatile(
        "mma.sync.aligned.m16n8k16.row.col.f32.f16.f16.f32 "
        "{%0,%1,%2,%3},{%4,%5,%6,%7},{%8,%9},{%0,%1,%2,%3};"
        : "+f"(d[0]), "+f"(d[1]), "+f"(d[2]), "+f"(d[3])
        : "r"(a0), "r"(a1), "r"(a2), "r"(a3), "r"(b0), "r"(b1));
}

#define TBYTES 16384          // one 128-row x 64-k half tile
#define TU32 4096             // same tile in uint32s
#define SROW 132              // fp32 staging row stride (floats)
#define NSTG 3                // pipeline stages

// async-copy one 128x64-half tile (128B/row); gmem k-pre-permuted; XOR swizzle
__device__ __forceinline__ void tile_async_h(uint32_t sdst, const __half* src,
                                             int ldh, int kc, int tid) {
#pragma unroll
    for (int t = 0; t < 4; t++) {
        int idx = tid + t * 256;          // 0..1023 16B chunks
        int r = idx >> 3, j = idx & 7;
        uint32_t dst = sdst + (uint32_t)(((r << 3) + (j ^ (r & 7))) << 4);
        const __half* s = src + (size_t)r * ldh + kc + j * 8;
        asm volatile("cp.async.cg.shared.global [%0], [%1], 16;" ::"r"(dst),
                     "l"(s));
    }
}

// fragment read: 16B = the 8 operand halves a lane needs for 2 k16-mmas
__device__ __forceinline__ uint4 fragh(const uint32_t* tile, int r, int j) {
    return *(const uint4*)(tile + r * 32 + ((j ^ (r & 7)) << 2));
}

// plain pass: one (A x B) over a 64-k chunk (same-acc distance already 16)
__device__ __forceinline__ void pass_h(const uint32_t* As, const uint32_t* Bs,
                                       float acc[4][4][4], int wm, int wn,
                                       int g, int c) {
#pragma unroll
    for (int sp = 0; sp < 2; sp++) {
        int j = sp * 4 + c;
        uint4 a0[4], a1[4], bb[4];
#pragma unroll
        for (int mt = 0; mt < 4; mt++) {
            int r0 = wm + mt * 16 + g;
            a0[mt] = fragh(As, r0, j);
            a1[mt] = fragh(As, r0 + 8, j);
        }
#pragma unroll
        for (int nt = 0; nt < 4; nt++) bb[nt] = fragh(Bs, wn + nt * 8 + g, j);
#pragma unroll
        for (int kk = 0; kk < 2; kk++)
#pragma unroll
            for (int mt = 0; mt < 4; mt++) {
                uint32_t A0 = kk ? a0[mt].z : a0[mt].x;
                uint32_t A2 = kk ? a0[mt].w : a0[mt].y;
                uint32_t A1 = kk ? a1[mt].z : a1[mt].x;
                uint32_t A3 = kk ? a1[mt].w : a1[mt].y;
#pragma unroll
                for (int nt = 0; nt < 4; nt++) {
                    uint32_t B0 = kk ? bb[nt].z : bb[nt].x;
                    uint32_t B1 = kk ? bb[nt].w : bb[nt].y;
                    mma16(acc[mt][nt], A0, A1, A2, A3, B0, B1);
                }
            }
    }
}

// split pass, LATENCY-SAFE ordering: for each k-step, issue each of the 3
// limb products across ALL 16 (mt,nt) accumulators before touching any
// accumulator again (same-acc reuse distance 16 instructions, not 1).
__device__ __forceinline__ void pass_split_h(
    const uint32_t* Ah, const uint32_t* Bh, const uint32_t* Al,
    const uint32_t* Bl, float acc[4][4][4], int wm, int wn, int g, int c) {
#pragma unroll
    for (int sp = 0; sp < 2; sp++) {
        int j = sp * 4 + c;
        uint4 ah0[4], ah1[4], al0[4], al1[4], bh[4], bl[4];
#pragma unroll
        for (int mt = 0; mt < 4; mt++) {
            int r0 = wm + mt * 16 + g;
            ah0[mt] = fragh(Ah, r0, j);
            ah1[mt] = fragh(Ah, r0 + 8, j);
            al0[mt] = fragh(Al, r0, j);
            al1[mt] = fragh(Al, r0 + 8, j);
        }
#pragma unroll
        for (int nt = 0; nt < 4; nt++) {
            int n = wn + nt * 8 + g;
            bh[nt] = fragh(Bh, n, j);
            bl[nt] = fragh(Bl, n, j);
        }
#pragma unroll
        for (int kk = 0; kk < 2; kk++) {
            // product 1: A_hi x B_hi, all 16 accumulators
#pragma unroll
            for (int mt = 0; mt < 4; mt++) {
                uint32_t H0 = kk ? ah0[mt].z : ah0[mt].x;
                uint32_t H2 = kk ? ah0[mt].w : ah0[mt].y;
                uint32_t H1 = kk ? ah1[mt].z : ah1[mt].x;
                uint32_t H3 = kk ? ah1[mt].w : ah1[mt].y;
#pragma unroll
                for (int nt = 0; nt < 4; nt++)
                    mma16(acc[mt][nt], H0, H1, H2, H3,
                          kk ? bh[nt].z : bh[nt].x, kk ? bh[nt].w : bh[nt].y);
            }
            // product 2: A_hi x B_lo, all 16 accumulators
#pragma unroll
            for (int mt = 0; mt < 4; mt++) {
                uint32_t H0 = kk ? ah0[mt].z : ah0[mt].x;
                uint32_t H2 = kk ? ah0[mt].w : ah0[mt].y;
                uint32_t H1 = kk ? ah1[mt].z : ah1[mt].x;
                uint32_t H3 = kk ? ah1[mt].w : ah1[mt].y;
#pragma unroll
                for (int nt = 0; nt < 4; nt++)
                    mma16(acc[mt][nt], H0, H1, H2, H3,
                          kk ? bl[nt].z : bl[nt].x, kk ? bl[nt].w : bl[nt].y);
            }
            // product 3: A_lo x B_hi, all 16 accumulators
#pragma unroll
            for (int mt = 0; mt < 4; mt++) {
                uint32_t L0 = kk ? al0[mt].z : al0[mt].x;
                uint32_t L2 = kk ? al0[mt].w : al0[mt].y;
                uint32_t L1 = kk ? al1[mt].z : al1[mt].x;
                uint32_t L3 = kk ? al1[mt].w : al1[mt].y;
#pragma unroll
                for (int nt = 0; nt < 4; nt++)
                    mma16(acc[mt][nt], L0, L1, L2, L3,
                          kk ? bh[nt].z : bh[nt].x, kk ? bh[nt].w : bh[nt].y);
            }
        }
    }
}

// ---------------------------------------------------------------------------
// fp16 m16n8k16 NT GEMM with 3-stage cp.async ring (prefetch distance 2).
// C[M,N] = A[M,K] @ B[N,K]^T (+bias). Operand k-dims gmem-pre-permuted.
// SPLIT: 3-product hi/lo limbs. outHalf: half output, column k-permuted.
// perm != 0: output row r -> (r&7)*SS + z*256 + (r>>3)   (torch .view fold)
// ---------------------------------------------------------------------------
template <bool SPLIT>
__global__ void __launch_bounds__(256, SPLIT ? 1 : 2)
hgemm(const __half* __restrict__ A0, const __half* __restrict__ A1,
      const __half* __restrict__ B0, const __half* __restrict__ B1,
      const float* __restrict__ bias, void* Cv, void* Clov,
      int M, int N, int K, int lda, int ldb, int ldc,
      long aZ, long bZ, long cZ, int perm, int outHalf) {
    extern __shared__ float smf[];
    uint32_t* smu = (uint32_t*)smf;
    const int NT = SPLIT ? 4 : 2;
    const uint32_t sb = smem_u32(smf);

    const int tid = threadIdx.x;
    const int warp = tid >> 5, lane = tid & 31;
    const int g = lane >> 2, c = lane & 3;
    const int m0 = blockIdx.y * 128, n0 = blockIdx.x * 128;
    const int z = blockIdx.z;
    const int wm = (warp >> 2) * 64;
    const int wn = (warp & 3) * 32;

    const __half* Ag = A0 + (size_t)z * aZ + (size_t)m0 * lda;
    const __half* Bg = B0 + (size_t)z * bZ + (size_t)n0 * ldb;
    const __half* Ag1 = SPLIT ? A1 + (size_t)z * aZ + (size_t)m0 * lda : nullptr;
    const __half* Bg1 = SPLIT ? B1 + (size_t)z * bZ + (size_t)n0 * ldb : nullptr;

    float acc[4][4][4];
#pragma unroll
    for (int i = 0; i < 4; i++)
#pragma unroll
        for (int j = 0; j < 4; j++)
#pragma unroll
            for (int k = 0; k < 4; k++) acc[i][j][k] = 0.0f;

    const int nchunks = K >> 6;

    // prologue: prefetch chunks 0 and 1
#pragma unroll
    for (int s = 0; s < 2; s++) {
        if (s < nchunks) {
            uint32_t bs = sb + (uint32_t)(s * NT * TBYTES);
            tile_async_h(bs, Ag, lda, s * 64, tid);
            tile_async_h(bs + TBYTES, Bg, ldb, s * 64, tid);
            if (SPLIT) {
                tile_async_h(bs + 2 * TBYTES, Ag1, lda, s * 64, tid);
                tile_async_h(bs + 3 * TBYTES, Bg1, ldb, s * 64, tid);
            }
            asm volatile("cp.async.commit_group;");
        }
    }

    int bufc = 0, buff = 2 % NSTG;
    for (int i = 0; i < nchunks; i++) {
        __syncthreads();    // all warps done with chunk i-1 (frees ring slot)
        int nf = i + 2;
        if (nf < nchunks) {
            uint32_t bs = sb + (uint32_t)(buff * NT * TBYTES);
            tile_async_h(bs, Ag, lda, nf * 64, tid);
            tile_async_h(bs + TBYTES, Bg, ldb, nf * 64, tid);
            if (SPLIT) {
                tile_async_h(bs + 2 * TBYTES, Ag1, lda, nf * 64, tid);
                tile_async_h(bs + 3 * TBYTES, Bg1, ldb, nf * 64, tid);
            }
            asm volatile("cp.async.commit_group;");
            asm volatile("cp.async.wait_group 2;");
        } else if (i + 1 < nchunks) {
            asm volatile("cp.async.wait_group 1;");
        } else {
            asm volatile("cp.async.wait_group 0;");
        }
        __syncthreads();    // chunk i visible to all warps

        const uint32_t* Ah = smu + bufc * NT * TU32;
        const uint32_t* Bh = Ah + TU32;
        if (SPLIT)
            pass_split_h(Ah, Bh, Ah + 2 * TU32, Ah + 3 * TU32, acc, wm, wn, g, c);
        else
            pass_h(Ah, Bh, acc, wm, wn, g, c);

        bufc = (bufc + 1) % NSTG;
        buff = (buff + 1) % NSTG;
    }

    // ---- staged epilogue: stage fp32 once per half-tile, flush coalesced ---
    float* stage = smf;
#pragma unroll 1
    for (int h128 = 0; h128 < 2; h128++) {
        __syncthreads();
        if ((warp >> 2) == h128) {
#pragma unroll
            for (int mt = 0; mt < 4; mt++)
#pragma unroll
                for (int hf = 0; hf < 2; hf++) {
                    int lrow = mt * 16 + g + hf * 8;
#pragma unroll
                    for (int nt = 0; nt < 4; nt++) {
                        int col = wn + nt * 8 + c * 2;
                        float v0 = acc[mt][nt][hf * 2 + 0];
                        float v1 = acc[mt][nt][hf * 2 + 1];
                        if (bias) {
                            v0 += bias[n0 + col];
                            v1 += bias[n0 + col + 1];
                        }
                        stage[lrow * SROW + col] = v0;
                        stage[lrow * SROW + col + 1] = v1;
                    }
                }
        }
        __syncthreads();

        if (outHalf) {
            __half* Cb = (__half*)Cv + (size_t)z * cZ;
            __half* Lb = Clov ? (__half*)Clov + (size_t)z * cZ : nullptr;
            const int nR = Lb ? 2 : 1;
#pragma unroll 1
            for (int rnd = 0; rnd < nR; rnd++) {
                __half* Ob = rnd ? Lb : Cb;
#pragma unroll
                for (int i = 0; i < 4; i++) {
                    int flat = tid + i * 256;
                    int jg = flat & 15, lrow = flat >> 4;
                    int row = m0 + h128 * 64 + lrow;
                    long crow = perm ? ((long)(row & 7) * SS + (long)z * 256 +
                                        (row >> 3))
                                     : (long)row;
                    int p0 = jg * 8;
                    int cc = (p0 >> 3) & 3, base = p0 & ~31;
                    const float* sr = stage + lrow * SROW + base + 2 * cc;
                    float f[8];
                    f[0] = sr[0];  f[1] = sr[1];
                    f[2] = sr[8];  f[3] = sr[9];
                    f[4] = sr[16]; f[5] = sr[17];
                    f[6] = sr[24]; f[7] = sr[25];
                    if (rnd) {
#pragma unroll
                        for (int e = 0; e < 8; e++) f[e] = lo_of(f[e]);
                    }
                    uint4 o;
                    o.x = pack2(f[0], f[1]);
                    o.y = pack2(f[2], f[3]);
                    o.z = pack2(f[4], f[5]);
                    o.w = pack2(f[6], f[7]);
                    *(uint4*)&Ob[crow * (long)ldc + n0 + p0] = o;
                }
            }
        } else {
            float* Ob = (float*)Cv + (size_t)z * cZ;
#pragma unroll
            for (int i = 0; i < 8; i++) {
                int flat = tid + i * 256;
                int jg = flat & 31, lrow = flat >> 5;
                int row = m0 + h128 * 64 + lrow;
                long crow = perm ? ((long)(row & 7) * SS + (long)z * 256 +
                                    (row >> 3))
                                 : (long)row;
                float4 v = *(const float4*)&stage[lrow * SROW + jg * 4];
                *(float4*)&Ob[crow * (long)ldc + n0 + jg * 4] = v;
            }
        }
    }
}

// ---------------- prep kernels ----------------------------------------------
__global__ void relenc1_split(const float* __restrict__ rel4,
                              const float* __restrict__ w1,
                              const float* __restrict__ b1,
                              __half* __restrict__ hi, __half* __restrict__ lo) {
    int idx = blockIdx.x * 256 + threadIdx.x;
    int s = idx >> 10, p = idx & 1023;
    int j = (p & ~31) | invp(p & 31);
    float acc = b1[j];
#pragma unroll
    for (int k = 0; k < 4; k++) acc = fmaf(rel4[s * 4 + k], w1[k * 1024 + j], acc);
    acc = fmaxf(acc, 0.0f);
    __half h = __float2half_rn(acc);
    hi[idx] = h;
    lo[idx] = __float2half_rn(acc - __half2float(h));
}

// fused transpose for re_w2 (z=0) + attn_w (z=1..8): out[c][perm(r)] half pair
__global__ void transpose_wqa(const float* __restrict__ w2,
                              const float* __restrict__ aw,
                              __half* __restrict__ w2hi, __half* __restrict__ w2lo,
                              __half* __restrict__ awhi, __half* __restrict__ awlo) {
    __shared__ float t[32][33];
    int z = blockIdx.z;
    const float* in = (z == 0) ? w2 : aw + (size_t)(z - 1) * DD * DD;
    __half* ohi = (z == 0) ? w2hi : awhi + (size_t)(z - 1) * DD * DD;
    __half* olo = (z == 0) ? w2lo : awlo + (size_t)(z - 1) * DD * DD;
    int r0 = blockIdx.y * 32, c0 = blockIdx.x * 32;
#pragma unroll
    for (int i = 0; i < 32; i += 8)
        t[threadIdx.y + i][threadIdx.x] =
            in[(size_t)(r0 + threadIdx.y + i) * DD + c0 + threadIdx.x];
    __syncthreads();
    int tx = threadIdx.x, sx = invp(tx);
#pragma unroll
    for (int i = 0; i < 32; i += 8) {
        float v = t[sx][threadIdx.y + i];
        size_t o = (size_t)(c0 + threadIdx.y + i) * DD + r0 + tx;
        __half h = __float2half_rn(v);
        ohi[o] = h;
        olo[o] = __float2half_rn(v - __half2float(h));
    }
}

// fused x prep: x_hi/lo [S][perm D]  AND  xt [D][perm S]
__global__ void prep_x(const float* __restrict__ x, __half* __restrict__ xhi,
                       __half* __restrict__ xlo, __half* __restrict__ xt) {
    __shared__ float t[32][33];
    int r0 = blockIdx.y * 32, c0 = blockIdx.x * 32;   // r over S, c over D
#pragma unroll
    for (int i = 0; i < 32; i += 8)
        t[threadIdx.y + i][threadIdx.x] =
            x[(size_t)(r0 + threadIdx.y + i) * DD + c0 + threadIdx.x];
    __syncthreads();
    int tx = threadIdx.x, sx = invp(tx);
#pragma unroll
    for (int i = 0; i < 32; i += 8) {
        float v = t[threadIdx.y + i][sx];
        size_t o = (size_t)(r0 + threadIdx.y + i) * DD + c0 + tx;
        __half h = __float2half_rn(v);
        xhi[o] = h;
        xlo[o] = __float2half_rn(v - __half2float(h));
        float u = t[sx][threadIdx.y + i];
        xt[(size_t)(c0 + threadIdx.y + i) * SS + r0 + tx] = __float2half_rn(u);
    }
}

// out_w [8192,1024] -> owt [1024][perm 8192], single limb
__global__ void transpose_owt(const float* __restrict__ in,
                              __half* __restrict__ ot) {
    __shared__ float t[32][33];
    int r0 = blockIdx.y * 32, c0 = blockIdx.x * 32;
#pragma unroll
    for (int i = 0; i < 32; i += 8)
        t[threadIdx.y + i][threadIdx.x] =
            in[(size_t)(r0 + threadIdx.y + i) * DD + c0 + threadIdx.x];
    __syncthreads();
    int tx = threadIdx.x, sx = invp(tx);
#pragma unroll
    for (int i = 0; i < 32; i += 8)
        ot[(size_t)(c0 + threadIdx.y + i) * (HH * DD) + r0 + tx] =
            __float2half_rn(t[sx][threadIdx.y + i]);
}

// ---------------- softmax: fp32 logits -> half probs (k-permuted) -----------
__global__ void softmax_kernel(const float* __restrict__ L,
                               __half* __restrict__ P) {
    const float* p = L + (size_t)blockIdx.x * SS;
    __half* q = P + (size_t)blockIdx.x * SS;
    const int tid = threadIdx.x;
    __shared__ float red[8];
    __shared__ float sbuf[SS];

    float4 v[2];
    v[0] = *(const float4*)&p[tid * 4];
    v[1] = *(const float4*)&p[1024 + tid * 4];

    float m = fmaxf(fmaxf(fmaxf(v[0].x, v[0].y), fmaxf(v[0].z, v[0].w)),
                    fmaxf(fmaxf(v[1].x, v[1].y), fmaxf(v[1].z, v[1].w)));
#pragma unroll
    for (int s = 16; s > 0; s >>= 1)
        m = fmaxf(m, __shfl_xor_sync(0xFFFFFFFF, m, s));
    if ((tid & 31) == 0) red[tid >> 5] = m;
    __syncthreads();
    m = fmaxf(fmaxf(fmaxf(red[0], red[1]), fmaxf(red[2], red[3])),
              fmaxf(fmaxf(red[4], red[5]), fmaxf(red[6], red[7])));
    __syncthreads();

    float sum = 0.0f;
#pragma unroll
    for (int h = 0; h < 2; h++) {
        float* f = (float*)&v[h];
#pragma unroll
        for (int e = 0; e < 4; e++) {
            f[e] = __expf(f[e] - m);
            sum += f[e];
        }
    }
#pragma unroll
    for (int s = 16; s > 0; s >>= 1) sum += __shfl_xor_sync(0xFFFFFFFF, sum, s);
    if ((tid & 31) == 0) red[tid >> 5] = sum;
    __syncthreads();
    sum = red[0] + red[1] + red[2] + red[3] + red[4] + red[5] + red[6] + red[7];
    float inv = 1.0f / sum;

#pragma unroll
    for (int h = 0; h < 2; h++) {
        float* f = (float*)&v[h];
#pragma unroll
        for (int e = 0; e < 4; e++)
            sbuf[h * 1024 + tid * 4 + e] = f[e] * inv;
    }
    __syncthreads();

    {
        int p0 = tid * 8;
        int cc = (p0 >> 3) & 3, base = p0 & ~31;
        const float* sr = sbuf + base + 2 * cc;
        uint4 o;
        o.x = pack2(sr[0], sr[1]);
        o.y = pack2(sr[8], sr[9]);
        o.z = pack2(sr[16], sr[17]);
        o.w = pack2(sr[24], sr[25]);
        *(uint4*)&q[p0] = o;
    }
}

// ---------------------------------------------------------------------------
extern "C" void kernel_launch(void* const* d_in, const int* in_sizes, int n_in,
                              void* d_out, int out_size) {
    const float* x         = (const float*)d_in[0];
    const float* relations = (const float*)d_in[1];
    const float* re_w1     = (const float*)d_in[2];
    const float* re_b1     = (const float*)d_in[3];
    const float* re_w2     = (const float*)d_in[4];
    const float* re_b2     = (const float*)d_in[5];
    const float* attn_w    = (const float*)d_in[6];
    const float* out_w     = (const float*)d_in[7];
    const float* out_b     = (const float*)d_in[8];
    float* out = (float*)d_out;

    __half *hid_hi, *hid_lo, *w2t_hi, *w2t_lo, *awt_hi, *awt_lo;
    __half *x_hi, *x_lo, *xt, *owt, *rel_hi, *rel_lo, *Q_hi, *Q_lo, *probs, *ctx;
    float* Lg;
    cudaGetSymbolAddress((void**)&hid_hi, g_hid_hi);
    cudaGetSymbolAddress((void**)&hid_lo, g_hid_lo);
    cudaGetSymbolAddress((void**)&w2t_hi, g_w2t_hi);
    cudaGetSymbolAddress((void**)&w2t_lo, g_w2t_lo);
    cudaGetSymbolAddress((void**)&awt_hi, g_awt_hi);
    cudaGetSymbolAddress((void**)&awt_lo, g_awt_lo);
    cudaGetSymbolAddress((void**)&x_hi, g_x_hi);
    cudaGetSymbolAddress((void**)&x_lo, g_x_lo);
    cudaGetSymbolAddress((void**)&xt, g_xt);
    cudaGetSymbolAddress((void**)&owt, g_owt);
    cudaGetSymbolAddress((void**)&rel_hi, g_rel_hi);
    cudaGetSymbolAddress((void**)&rel_lo, g_rel_lo);
    cudaGetSymbolAddress((void**)&Q_hi, g_Q_hi);
    cudaGetSymbolAddress((void**)&Q_lo, g_Q_lo);
    cudaGetSymbolAddress((void**)&Lg, g_logits);
    cudaGetSymbolAddress((void**)&probs, g_probs);
    cudaGetSymbolAddress((void**)&ctx, g_ctx);

    const int SM_SPLIT = NSTG * 4 * TBYTES;   // 196608 B, 1 CTA/SM
    const int SM_PLAIN = NSTG * 2 * TBYTES;   // 98304 B, 2 CTAs/SM
    cudaFuncSetAttribute(hgemm<true>, cudaFuncAttributeMaxDynamicSharedMemorySize,
                         SM_SPLIT);
    cudaFuncSetAttribute(hgemm<false>, cudaFuncAttributeMaxDynamicSharedMemorySize,
                         SM_PLAIN);

    relenc1_split<<<(SS * DD) / 256, 256>>>(relations, re_w1, re_b1, hid_hi,
                                            hid_lo);
    transpose_wqa<<<dim3(32, 32, 9), dim3(32, 8)>>>(re_w2, attn_w, w2t_hi,
                                                    w2t_lo, awt_hi, awt_lo);
    hgemm<true><<<dim3(8, 16, 1), 256, SM_SPLIT>>>(
        hid_hi, hid_lo, w2t_hi, w2t_lo, re_b2, rel_hi, rel_lo,
        SS, DD, DD, DD, DD, DD, 0, 0, 0, 0, 1);
    prep_x<<<dim3(32, 64), dim3(32, 8)>>>(x, x_hi, x_lo, xt);
    hgemm<true><<<dim3(8, 16, 8), 256, SM_SPLIT>>>(
        x_hi, x_lo, awt_hi, awt_lo, nullptr, Q_hi, Q_lo,
        SS, DD, DD, DD, DD, DD, 0, (long)DD * DD, 0, 1, 1);
    hgemm<true><<<dim3(16, 16, 8), 256, SM_SPLIT>>>(
        rel_hi, rel_lo, Q_hi, Q_lo, nullptr, Lg, nullptr,
        SS, SS, DD, DD, DD, SS, 0, (long)SS * DD, (long)SS * SS, 0, 0);
    softmax_kernel<<<HH * SS, 256>>>(Lg, probs);
    hgemm<false><<<dim3(8, 16, 8), 256, SM_PLAIN>>>(
        probs, nullptr, xt, nullptr, nullptr, ctx, nullptr,
        SS, DD, SS, SS, SS, HH * DD, (long)SS * SS, 0, (long)DD, 0, 1);
    transpose_owt<<<dim3(32, 256), dim3(32, 8)>>>(out_w, owt);
    hgemm<false><<<dim3(8, 16, 1), 256, SM_PLAIN>>>(
        ctx, nullptr, owt, nullptr, out_b, out, nullptr,
        SS, DD, HH * DD, HH * DD, HH * DD, DD, 0, 0, 0, 0, 0);
}